// round 17
// baseline (speedup 1.0000x reference)
#include <cuda_runtime.h>

#define TT 512
#define BTILE 16
#define NTHREADS 512

typedef unsigned long long ull;

struct Smem {
    float w0[64 * 256];    // [k][j*4+gate] <- w_hh0[(gate*64+j)*64+k]
    float wi1[64 * 256];   // same regroup of w_ih1
    float wh1[64 * 256];   // same regroup of w_hh1
    float hA[2][64 * 16];  // layer-0 hidden, [buf][k*16 + b]
    float hB[2][64 * 16];  // layer-1 hidden
    float xs[2][BTILE * 4];
};

__device__ __forceinline__ ull pack2(float x, float y) {
    ull r;
    asm("mov.b64 %0, {%1, %2};" : "=l"(r) : "f"(x), "f"(y));
    return r;
}
__device__ __forceinline__ void unpack2(ull v, float& x, float& y) {
    asm("mov.b64 {%0, %1}, %2;" : "=f"(x), "=f"(y) : "l"(v));
}
__device__ __forceinline__ ull fma2(ull a, ull b, ull c) {
    ull d;
    asm("fma.rn.f32x2 %0, %1, %2, %3;" : "=l"(d) : "l"(a), "l"(b), "l"(c));
    return d;
}
__device__ __forceinline__ float tanh_ap(float x) {
    float y;
    asm("tanh.approx.f32 %0, %1;" : "=f"(y) : "f"(x));
    return y;
}
__device__ __forceinline__ float sig_ap(float x) {
    return fmaf(tanh_ap(x * 0.5f), 0.5f, 0.5f);
}

// one cell from gate-pair accumulators (I,F) and (G,O); returns new h
__device__ __forceinline__ float cellh(ull aIF, ull aGO, float& c) {
    float gi, gf, gg, go;
    unpack2(aIF, gi, gf);
    unpack2(aGO, gg, go);
    float I = sig_ap(gi), F = sig_ap(gf), G = tanh_ap(gg), O = sig_ap(go);
    c = F * c + I * G;
    return O * tanh_ap(c);
}

__global__ void __launch_bounds__(NTHREADS, 1)
lstm_fused_kernel(const float* __restrict__ x,
                  const float* __restrict__ w_ih0, const float* __restrict__ w_hh0,
                  const float* __restrict__ b_ih0, const float* __restrict__ b_hh0,
                  const float* __restrict__ w_ih1, const float* __restrict__ w_hh1,
                  const float* __restrict__ b_ih1, const float* __restrict__ b_hh1,
                  const float* __restrict__ fc_w, const float* __restrict__ fc_b,
                  float* __restrict__ out)
{
    extern __shared__ __align__(16) unsigned char smem_raw[];
    Smem& sh = *reinterpret_cast<Smem*>(smem_raw);
    const int tid = threadIdx.x;
    const int b0 = blockIdx.x * BTILE;

    // ---- stage recurrent weights, regrouped: [k][j*4+gate] ----
    for (int e = tid; e < 64 * 256; e += NTHREADS) {
        int row = e >> 6, k = e & 63;
        int gate = row >> 6, jj = row & 63;
        int d = k * 256 + jj * 4 + gate;
        sh.w0[d] = w_hh0[e];
        sh.wi1[d] = w_ih1[e];
        sh.wh1[d] = w_hh1[e];
    }
    // ---- zero h buffers ----
    for (int e = tid; e < 1024; e += NTHREADS) {
        sh.hA[0][e] = 0.f; sh.hA[1][e] = 0.f;
        sh.hB[0][e] = 0.f; sh.hB[1][e] = 0.f;
    }
    // ---- preload x for t=0 ----
    if (tid < BTILE)
        *(float4*)&sh.xs[0][tid * 4] = ((const float4*)x)[(size_t)(b0 + tid) * TT];

    const int wid = tid >> 5;
    const int lane = tid & 31;
    // thread = (hidden unit j, 2 batch rows). 16 identical warps.
    const int j = (wid >> 1) * 8 + (lane >> 2);        // 0..63
    const int row0 = (((wid & 1) * 4) + (lane & 3)) * 2; // 0,2,..,14

    float wi0[16], bias0[4];
#pragma unroll
    for (int g = 0; g < 4; g++) {
        float4 wv = *(const float4*)(w_ih0 + (g * 64 + j) * 4);
        wi0[g * 4 + 0] = wv.x; wi0[g * 4 + 1] = wv.y;
        wi0[g * 4 + 2] = wv.z; wi0[g * 4 + 3] = wv.w;
        bias0[g] = b_ih0[g * 64 + j] + b_hh0[g * 64 + j];
    }
    ull biasIF, biasGO;
    {
        float bi = b_ih1[0 * 64 + j] + b_hh1[0 * 64 + j];
        float bf = b_ih1[1 * 64 + j] + b_hh1[1 * 64 + j];
        float bg = b_ih1[2 * 64 + j] + b_hh1[2 * 64 + j];
        float bo = b_ih1[3 * 64 + j] + b_hh1[3 * 64 + j];
        biasIF = pack2(bi, bf);
        biasGO = pack2(bg, bo);
    }
    float c[4];   // c[0..1]: layer-0 cells; c[2..3]: layer-1 cells
#pragma unroll
    for (int i = 0; i < 4; i++) c[i] = 0.f;

    __syncthreads();

    // ============ pipelined recurrence, self-contained threads ============
    // round r: this thread computes layer-0 step t=r AND layer-1 step t=r-1
    // for its (j, rows row0..row0+1). No intra-round communication at all.
    for (int r = 0; r <= TT; r++) {
        float4 xpre;
        const bool pre = (tid < BTILE) && (r <= TT - 2);
        if (pre) xpre = ((const float4*)x)[(size_t)(b0 + tid) * TT + (r + 1)];

        // layer-0 accumulators seeded with bias + x projection
        ull a0IF[2], a0GO[2], a1IF[2], a1GO[2];
        {
            const float4* xp = (const float4*)sh.xs[r & 1];
#pragma unroll
            for (int b = 0; b < 2; b++) {
                float4 xv = xp[row0 + b];
                float si = bias0[0] + wi0[0]*xv.x + wi0[1]*xv.y + wi0[2]*xv.z + wi0[3]*xv.w;
                float sf = bias0[1] + wi0[4]*xv.x + wi0[5]*xv.y + wi0[6]*xv.z + wi0[7]*xv.w;
                float sg = bias0[2] + wi0[8]*xv.x + wi0[9]*xv.y + wi0[10]*xv.z + wi0[11]*xv.w;
                float so = bias0[3] + wi0[12]*xv.x + wi0[13]*xv.y + wi0[14]*xv.z + wi0[15]*xv.w;
                a0IF[b] = pack2(si, sf);
                a0GO[b] = pack2(sg, so);
                a1IF[b] = biasIF;
                a1GO[b] = biasGO;
            }
        }
        const float* ha = sh.hA[r & 1] + row0;
        const float* hb = sh.hB[r & 1] + row0;
        const float* wp0 = sh.w0 + j * 4;
        const float* wp1 = sh.wi1 + j * 4;
        const float* wp2 = sh.wh1 + j * 4;
        // per k: 2 LDS.64 (h) + 3 LDS.128 (w) + 4 packs + 12 fma2.
        // ih1 and hh1 accumulate into the SAME layer-1 registers.
#pragma unroll 8
        for (int k = 0; k < 64; k++) {
            float2 hva = *(const float2*)(ha + k * 16);
            ull hd0 = pack2(hva.x, hva.x);
            ull hd1 = pack2(hva.y, hva.y);
            ulonglong2 w0v = *(const ulonglong2*)(wp0 + (k << 8)); // (wI,wF),(wG,wO)
            a0IF[0] = fma2(hd0, w0v.x, a0IF[0]); a0GO[0] = fma2(hd0, w0v.y, a0GO[0]);
            a0IF[1] = fma2(hd1, w0v.x, a0IF[1]); a0GO[1] = fma2(hd1, w0v.y, a0GO[1]);
            ulonglong2 w1v = *(const ulonglong2*)(wp1 + (k << 8));
            a1IF[0] = fma2(hd0, w1v.x, a1IF[0]); a1GO[0] = fma2(hd0, w1v.y, a1GO[0]);
            a1IF[1] = fma2(hd1, w1v.x, a1IF[1]); a1GO[1] = fma2(hd1, w1v.y, a1GO[1]);
            float2 hvb = *(const float2*)(hb + k * 16);
            ull he0 = pack2(hvb.x, hvb.x);
            ull he1 = pack2(hvb.y, hvb.y);
            ulonglong2 w2v = *(const ulonglong2*)(wp2 + (k << 8));
            a1IF[0] = fma2(he0, w2v.x, a1IF[0]); a1GO[0] = fma2(he0, w2v.y, a1GO[0]);
            a1IF[1] = fma2(he1, w2v.x, a1IF[1]); a1GO[1] = fma2(he1, w2v.y, a1GO[1]);
        }
        if (r < TT) {
            float2 hn;
            hn.x = cellh(a0IF[0], a0GO[0], c[0]);
            hn.y = cellh(a0IF[1], a0GO[1], c[1]);
            *(float2*)(sh.hA[(r + 1) & 1] + j * 16 + row0) = hn;
        }
        if (r >= 1) {
            float2 hn;
            hn.x = cellh(a1IF[0], a1GO[0], c[2]);
            hn.y = cellh(a1IF[1], a1GO[1], c[3]);
            *(float2*)(sh.hB[(r + 1) & 1] + j * 16 + row0) = hn;
        }
        if (pre) *(float4*)&sh.xs[(r + 1) & 1][tid * 4] = xpre;
        __syncthreads();
    }

    // ============ FC + tanh epilogue ============
    // h_n (layer 1, t=511) finalized at r=512 -> hB[1].
    for (int e = tid; e < 4096; e += NTHREADS) {
        int jj = e >> 6, k = e & 63;
        sh.w0[k * 64 + jj] = fc_w[e]; // transpose: [k][j]
    }
    __syncthreads();

    if (tid < 256) {
        const int q = tid >> 6;  // 4 batch rows each
        const int jo = tid & 63;
        const float* hfin = sh.hB[1];
        float fb = fc_b[jo];
        float acc[4];
#pragma unroll
        for (int m = 0; m < 4; m++) acc[m] = fb;
#pragma unroll 8
        for (int k = 0; k < 64; k++) {
            float w = sh.w0[k * 64 + jo];
#pragma unroll
            for (int m = 0; m < 4; m++)
                acc[m] += w * hfin[k * 16 + q * 4 + m];
        }
#pragma unroll
        for (int m = 0; m < 4; m++)
            out[(size_t)(b0 + q * 4 + m) * 64 + jo] = tanh_ap(acc[m]);
    }
}

extern "C" void kernel_launch(void* const* d_in, const int* in_sizes, int n_in,
                              void* d_out, int out_size) {
    const float* x     = (const float*)d_in[0];
    const float* w_ih0 = (const float*)d_in[1];
    const float* w_hh0 = (const float*)d_in[2];
    const float* b_ih0 = (const float*)d_in[3];
    const float* b_hh0 = (const float*)d_in[4];
    const float* w_ih1 = (const float*)d_in[5];
    const float* w_hh1 = (const float*)d_in[6];
    const float* b_ih1 = (const float*)d_in[7];
    const float* b_hh1 = (const float*)d_in[8];
    const float* fc_w  = (const float*)d_in[9];
    const float* fc_b  = (const float*)d_in[10];
    float* out = (float*)d_out;

    const int smem = (int)sizeof(Smem);
    cudaFuncSetAttribute(lstm_fused_kernel,
                         cudaFuncAttributeMaxDynamicSharedMemorySize, smem);
    lstm_fused_kernel<<<2048 / BTILE, NTHREADS, smem>>>(
        x, w_ih0, w_hh0, b_ih0, b_hh0,
        w_ih1, w_hh1, b_ih1, b_hh1, fc_w, fc_b, out);
}